// round 2
// baseline (speedup 1.0000x reference)
#include <cuda_runtime.h>
#include <cuda_bf16.h>
#include <cstdint>

// Problem constants (fixed-shape problem)
#define BATCH 4
#define HH 128
#define WW 128
#define TT (HH * WW)          // 16384
#define CC 256
#define NTOT (BATCH * TT)     // 65536

// ---------------- scratch (static device globals; allowed) ----------------
__device__ float g_mid[(size_t)NTOT * CC];          // conv1 output        (N,256)
__device__ float g_dcat[(size_t)NTOT * 3 * CC];     // depthwise outputs   (N,768)
__device__ float g_xx[(size_t)NTOT * CC];           // shifted features    (N,256)
__device__ float g_kvr[(size_t)NTOT * 3 * CC];      // k|v|r               (N,768)
__device__ float g_y[(size_t)NTOT * CC];            // wkv output          (N,256)
__device__ float g_gt[(size_t)NTOT * CC];           // gated LN output     (N,256)
__device__ float g_Wp[CC * 3 * CC];                 // merged proj weight  (256,768)
__device__ float g_Wkvr[3 * CC * CC];               // merged kvr weight   (768,256)
__device__ float g_mixcat[3 * CC];
__device__ float g_wneg[CC];
__device__ float g_u[CC];

// ---------------- prep: build merged weights + wkv constants ----------------
__global__ void prep_kernel(const float* __restrict__ proj1, const float* __restrict__ proj2,
                            const float* __restrict__ proj3,
                            const float* __restrict__ keyw, const float* __restrict__ valw,
                            const float* __restrict__ recw,
                            const float* __restrict__ mixk, const float* __restrict__ mixv,
                            const float* __restrict__ mixr,
                            const float* __restrict__ decay, const float* __restrict__ first)
{
    int i = blockIdx.x * blockDim.x + threadIdx.x;
    if (i < CC * 3 * CC) {
        // Wp[o, j*256+c] = proj_j[o,c]
        int o = i / (3 * CC);
        int rem = i % (3 * CC);
        int j = rem >> 8;
        int c = rem & 255;
        const float* p = (j == 0) ? proj1 : (j == 1) ? proj2 : proj3;
        g_Wp[i] = p[o * CC + c];
        // Wkvr = [key_w ; value_w ; recep_w]  (768 x 256)
        g_Wkvr[i] = (i < CC * CC) ? keyw[i]
                  : (i < 2 * CC * CC) ? valw[i - CC * CC]
                  : recw[i - 2 * CC * CC];
    }
    if (i < 3 * CC)
        g_mixcat[i] = (i < CC) ? mixk[i] : (i < 2 * CC) ? mixv[i - CC] : mixr[i - 2 * CC];
    if (i < CC) {
        g_wneg[i] = -expf(decay[i] * (1.0f / (float)TT));
        g_u[i]    = first[i] * (1.0f / (float)TT);
    }
}

// ---------------- SGEMM: out(N,M) = A(N,K) * W(M,K)^T  [+ epilogue] ----------------
// MODE 0: plain     MODE 1: out += addsrc(N,M)     MODE 2: A = mix*A + (1-mix)*A2
#define GBM 128
#define GBN 128
#define GBK 16

template <int MODE>
__device__ __forceinline__ void
sgemm_body(const float* __restrict__ A, const float* __restrict__ A2,
           const float* __restrict__ Wt, const float* __restrict__ mixcat,
           const float* __restrict__ addsrc, float* __restrict__ Cout,
           int M, int K)
{
    __shared__ float As[GBK][GBN + 4];
    __shared__ float Ws[GBK][GBM + 4];

    const int tid = threadIdx.x;
    const size_t n0 = (size_t)blockIdx.x * GBN;
    const int m0 = blockIdx.y * GBM;

    const int lr = tid >> 1;          // 0..127 : row within tile
    const int lk = (tid & 1) * 8;     // 0 or 8 : k offset

    const float* Arow = A + (n0 + lr) * (size_t)K;
    const float* A2row = (MODE == 2) ? (A2 + (n0 + lr) * (size_t)K) : nullptr;
    const float* Wrow = Wt + (size_t)(m0 + lr) * K;
    const float* mixp = (MODE == 2) ? (mixcat + (m0 >> 8) * CC) : nullptr;

    float ra[8], rw[8];

    auto ldA = [&](int k0) {
        if (MODE == 2) {
            float4 vx0 = *(const float4*)(Arow + k0 + lk);
            float4 vx1 = *(const float4*)(Arow + k0 + lk + 4);
            float4 vy0 = *(const float4*)(A2row + k0 + lk);
            float4 vy1 = *(const float4*)(A2row + k0 + lk + 4);
            float4 m0v = *(const float4*)(mixp + k0 + lk);
            float4 m1v = *(const float4*)(mixp + k0 + lk + 4);
            ra[0] = m0v.x * vx0.x + (1.f - m0v.x) * vy0.x;
            ra[1] = m0v.y * vx0.y + (1.f - m0v.y) * vy0.y;
            ra[2] = m0v.z * vx0.z + (1.f - m0v.z) * vy0.z;
            ra[3] = m0v.w * vx0.w + (1.f - m0v.w) * vy0.w;
            ra[4] = m1v.x * vx1.x + (1.f - m1v.x) * vy1.x;
            ra[5] = m1v.y * vx1.y + (1.f - m1v.y) * vy1.y;
            ra[6] = m1v.z * vx1.z + (1.f - m1v.z) * vy1.z;
            ra[7] = m1v.w * vx1.w + (1.f - m1v.w) * vy1.w;
        } else {
            float4 v0 = *(const float4*)(Arow + k0 + lk);
            float4 v1 = *(const float4*)(Arow + k0 + lk + 4);
            ra[0] = v0.x; ra[1] = v0.y; ra[2] = v0.z; ra[3] = v0.w;
            ra[4] = v1.x; ra[5] = v1.y; ra[6] = v1.z; ra[7] = v1.w;
        }
    };
    auto ldW = [&](int k0) {
        float4 v0 = *(const float4*)(Wrow + k0 + lk);
        float4 v1 = *(const float4*)(Wrow + k0 + lk + 4);
        rw[0] = v0.x; rw[1] = v0.y; rw[2] = v0.z; rw[3] = v0.w;
        rw[4] = v1.x; rw[5] = v1.y; rw[6] = v1.z; rw[7] = v1.w;
    };

    ldA(0);
    ldW(0);

    float acc[8][8];
#pragma unroll
    for (int i = 0; i < 8; ++i)
#pragma unroll
        for (int j = 0; j < 8; ++j) acc[i][j] = 0.f;

    const int tx = tid & 15;   // m-frag
    const int ty = tid >> 4;   // n-frag

    for (int k0 = 0;;) {
        __syncthreads();
#pragma unroll
        for (int j = 0; j < 8; ++j) {
            As[lk + j][lr] = ra[j];
            Ws[lk + j][lr] = rw[j];
        }
        __syncthreads();
        k0 += GBK;
        if (k0 < K) { ldA(k0); ldW(k0); }

#pragma unroll
        for (int kk = 0; kk < GBK; ++kk) {
            float a[8], w[8];
            *(float4*)(a)     = *(const float4*)&As[kk][ty * 8];
            *(float4*)(a + 4) = *(const float4*)&As[kk][ty * 8 + 4];
            *(float4*)(w)     = *(const float4*)&Ws[kk][tx * 8];
            *(float4*)(w + 4) = *(const float4*)&Ws[kk][tx * 8 + 4];
#pragma unroll
            for (int i = 0; i < 8; ++i)
#pragma unroll
                for (int j = 0; j < 8; ++j)
                    acc[i][j] = fmaf(a[i], w[j], acc[i][j]);
        }
        if (k0 >= K) break;
    }

#pragma unroll
    for (int i = 0; i < 8; ++i) {
        size_t n = n0 + ty * 8 + i;
        float* op = Cout + n * (size_t)M + m0 + tx * 8;
        float v[8];
#pragma unroll
        for (int j = 0; j < 8; ++j) v[j] = acc[i][j];
        if (MODE == 1) {
            const float* ap = addsrc + n * (size_t)M + m0 + tx * 8;
#pragma unroll
            for (int j = 0; j < 8; ++j) v[j] += ap[j];
        }
        *(float4*)(op)     = make_float4(v[0], v[1], v[2], v[3]);
        *(float4*)(op + 4) = make_float4(v[4], v[5], v[6], v[7]);
    }
}

// Thin wrappers binding scratch globals at compile time (no host-side symbol lookup).
__global__ void __launch_bounds__(256, 2)
gemm_conv1(const float* __restrict__ x, const float* __restrict__ conv1w)
{
    sgemm_body<0>(x, nullptr, conv1w, nullptr, nullptr, g_mid, 256, 256);
}
__global__ void __launch_bounds__(256, 2)
gemm_projsum(const float* __restrict__ x)
{
    sgemm_body<1>(g_dcat, nullptr, g_Wp, nullptr, x, g_xx, 256, 768);
}
__global__ void __launch_bounds__(256, 2)
gemm_kvr(const float* __restrict__ x)
{
    sgemm_body<2>(x, g_xx, g_Wkvr, g_mixcat, nullptr, g_kvr, 768, 256);
}
__global__ void __launch_bounds__(256, 2)
gemm_out(const float* __restrict__ outw, float* __restrict__ out)
{
    sgemm_body<0>(g_gt, nullptr, outw, nullptr, nullptr, out, 256, 256);
}

// ---------------- fused depthwise 3x3 (dilations 1,2,3) ----------------
// block: 32-channel slab x 8x8 spatial tile; halo 3 -> 14x14 patch in smem
__global__ void __launch_bounds__(256)
dwconv_kernel(const float* __restrict__ dw1, const float* __restrict__ dw2,
              const float* __restrict__ dw3)
{
    __shared__ float s[14 * 14 * 32];   // 25088 B
    __shared__ float sw[3 * 32 * 9];    // 3456 B

    const int tid = threadIdx.x;
    const int tile = blockIdx.x;        // 0..255
    const int b = blockIdx.y;           // 0..3
    const int cslab = blockIdx.z;       // 0..7
    const int th = tile >> 4, tw = tile & 15;
    const int h0 = th * 8 - 3, w0 = tw * 8 - 3;
    const int cbase = cslab * 32;

    for (int f = tid; f < 864; f += 256) {
        int j = f / 288, rem = f % 288;
        int c = rem / 9, tap = rem % 9;
        const float* wsrc = (j == 0) ? dw1 : (j == 1) ? dw2 : dw3;
        sw[f] = wsrc[(cbase + c) * 9 + tap];
    }

    const int lane = tid & 31, warp = tid >> 5;
    for (int p = warp; p < 196; p += 8) {
        int hy = p / 14, wx = p % 14;
        int h = h0 + hy, w = w0 + wx;
        float v = 0.f;
        if ((unsigned)h < (unsigned)HH && (unsigned)w < (unsigned)WW)
            v = g_mid[((size_t)(b * TT + h * WW + w)) * CC + cbase + lane];
        s[p * 32 + lane] = v;
    }
    __syncthreads();

    const float* w0p = &sw[lane * 9];
    const float* w1p = &sw[288 + lane * 9];
    const float* w2p = &sw[576 + lane * 9];

#pragma unroll
    for (int q = 0; q < 8; ++q) {
        const int oh = warp, ow = q;
        const int hy = oh + 3, wx = ow + 3;
        float acc0 = 0.f, acc1 = 0.f, acc2 = 0.f;
#pragma unroll
        for (int dy = -1; dy <= 1; ++dy) {
#pragma unroll
            for (int dx = -1; dx <= 1; ++dx) {
                int tap = (dy + 1) * 3 + (dx + 1);
                acc0 = fmaf(w0p[tap], s[((hy + dy) * 14 + (wx + dx)) * 32 + lane], acc0);
                acc1 = fmaf(w1p[tap], s[((hy + 2 * dy) * 14 + (wx + 2 * dx)) * 32 + lane], acc1);
                acc2 = fmaf(w2p[tap], s[((hy + 3 * dy) * 14 + (wx + 3 * dx)) * 32 + lane], acc2);
            }
        }
        size_t n = (size_t)b * TT + (size_t)(th * 8 + oh) * WW + (tw * 8 + ow);
        g_dcat[n * 768 + cbase + lane] = acc0;
        g_dcat[n * 768 + 256 + cbase + lane] = acc1;
        g_dcat[n * 768 + 512 + cbase + lane] = acc2;
    }
}

// ---------------- WKV: halo-recompute chunked scan ----------------
// per-step decay multiplier = exp(wneg) ~ e^-1  (decay/T ~ 0  =>  wneg ~ -1),
// so a 96-step warmup attenuates the truncated prefix by ~e^-96 (~2e-42):
// exact to fp32.
#define WKV_CHUNK 128
#define WKV_HALO 96

__global__ void __launch_bounds__(256)
wkv_kernel()
{
    const int c = threadIdx.x;
    const int b = blockIdx.y;
    const int chunk = blockIdx.x;
    const float wn = g_wneg[c];
    const float uu = g_u[c];

    const int t0 = chunk * WKV_CHUNK;
    int ts = t0 - WKV_HALO;
    if (ts < 0) ts = 0;

    float aa = 0.f, bb = 0.f, pp = -1e38f;

    const float* kv = g_kvr + ((size_t)b * TT + ts) * 768;
    for (int t = ts; t < t0; ++t, kv += 768) {
        float kk = kv[c], vv = kv[256 + c];
        float ww2 = wn + pp;
        if (kk >= ww2) {
            float e = __expf(ww2 - kk);
            aa = fmaf(aa, e, vv);
            bb = fmaf(bb, e, 1.f);
            pp = kk;
        } else {
            float e = __expf(kk - ww2);
            aa = fmaf(e, vv, aa);
            bb += e;
            pp = ww2;
        }
    }

    float* yp = g_y + ((size_t)b * TT + t0) * CC;
#pragma unroll 4
    for (int t = 0; t < WKV_CHUNK; ++t, kv += 768, yp += CC) {
        float kk = kv[c], vv = kv[256 + c];
        float ww = uu + kk;
        float y;
        if (pp >= ww) {
            float e = __expf(ww - pp);
            y = fmaf(e, vv, aa) / (bb + e);
        } else {
            float e = __expf(pp - ww);
            y = fmaf(e, aa, vv) / fmaf(e, bb, 1.f);
        }
        yp[c] = y;

        float ww2 = wn + pp;
        if (kk >= ww2) {
            float e = __expf(ww2 - kk);
            aa = fmaf(aa, e, vv);
            bb = fmaf(bb, e, 1.f);
            pp = kk;
        } else {
            float e = __expf(kk - ww2);
            aa = fmaf(e, vv, aa);
            bb += e;
            pp = ww2;
        }
    }
}

// ---------------- LayerNorm + sigmoid gate ----------------
__global__ void __launch_bounds__(256)
lngate_kernel(const float* __restrict__ gamma, const float* __restrict__ beta)
{
    const int warp = threadIdx.x >> 5, lane = threadIdx.x & 31;
    const size_t row = (size_t)blockIdx.x * 8 + warp;

    const float* yp = g_y + row * CC;
    float v[8];
    float sum = 0.f;
#pragma unroll
    for (int i = 0; i < 8; ++i) {
        v[i] = yp[lane + 32 * i];
        sum += v[i];
    }
#pragma unroll
    for (int o = 16; o; o >>= 1) sum += __shfl_xor_sync(0xffffffffu, sum, o);
    const float mu = sum * (1.f / 256.f);

    float var = 0.f;
#pragma unroll
    for (int i = 0; i < 8; ++i) {
        float d = v[i] - mu;
        var += d * d;
    }
#pragma unroll
    for (int o = 16; o; o >>= 1) var += __shfl_xor_sync(0xffffffffu, var, o);
    const float rstd = rsqrtf(var * (1.f / 256.f) + 1e-5f);

    const float* rp = g_kvr + row * 768 + 512;
    float* gp = g_gt + row * CC;
#pragma unroll
    for (int i = 0; i < 8; ++i) {
        int c = lane + 32 * i;
        float rr = rp[c];
        float sr = 1.f / (1.f + __expf(-rr));
        gp[c] = sr * ((v[i] - mu) * rstd * gamma[c] + beta[c]);
    }
}

// ---------------- launch: pure kernel launches, nothing else ----------------
extern "C" void kernel_launch(void* const* d_in, const int* in_sizes, int n_in,
                              void* d_out, int out_size)
{
    const float* x      = (const float*)d_in[0];
    const float* conv1w = (const float*)d_in[1];
    const float* dw1    = (const float*)d_in[2];
    const float* dw2    = (const float*)d_in[3];
    const float* dw3    = (const float*)d_in[4];
    const float* proj1  = (const float*)d_in[5];
    const float* proj2  = (const float*)d_in[6];
    const float* proj3  = (const float*)d_in[7];
    const float* decay  = (const float*)d_in[8];
    const float* first  = (const float*)d_in[9];
    const float* mixk   = (const float*)d_in[10];
    const float* mixv   = (const float*)d_in[11];
    const float* mixr   = (const float*)d_in[12];
    const float* keyw   = (const float*)d_in[13];
    const float* valw   = (const float*)d_in[14];
    const float* recw   = (const float*)d_in[15];
    const float* outw   = (const float*)d_in[16];
    const float* gamma  = (const float*)d_in[17];
    const float* beta   = (const float*)d_in[18];
    float* out = (float*)d_out;

    prep_kernel<<<768, 256>>>(proj1, proj2, proj3, keyw, valw, recw,
                              mixk, mixv, mixr, decay, first);

    dim3 g2(NTOT / GBN, 2);   // M = 256
    dim3 g6(NTOT / GBN, 6);   // M = 768

    gemm_conv1<<<g2, 256>>>(x, conv1w);                       // mid = x @ conv1^T
    dwconv_kernel<<<dim3(256, 4, 8), 256>>>(dw1, dw2, dw3);   // dcat (N,768)
    gemm_projsum<<<g2, 256>>>(x);                             // xx = x + dcat @ Wp^T
    gemm_kvr<<<g6, 256>>>(x);                                 // kvr (fused mix)
    wkv_kernel<<<dim3(TT / WKV_CHUNK, BATCH), 256>>>();       // wkv scan
    lngate_kernel<<<NTOT / 8, 256>>>(gamma, beta);            // LN + sigmoid gate
    gemm_out<<<g2, 256>>>(outw, out);                         // out = gt @ out_w^T
}

// round 4
// speedup vs baseline: 1.4744x; 1.4744x over previous
#include <cuda_runtime.h>
#include <cuda_bf16.h>
#include <cstdint>

// Problem constants (fixed-shape problem)
#define BATCH 4
#define HH 128
#define WW 128
#define TT (HH * WW)          // 16384
#define CC 256
#define NTOT (BATCH * TT)     // 65536

typedef __nv_bfloat16 bf16;
typedef __nv_bfloat162 bf162;

// ---------------- scratch (static device globals; allowed) ----------------
__device__ __align__(256) float g_mid[(size_t)NTOT * CC];       // conv1 out fp32 (dwconv input)
__device__ __align__(256) float g_kvr[(size_t)NTOT * 3 * CC];   // k|v|r fp32
__device__ __align__(256) float g_y[(size_t)NTOT * CC];         // wkv out fp32

__device__ __align__(256) bf16 g_xs   [(size_t)NTOT * 512];     // x split    [h(256)|l(256)]
__device__ __align__(256) bf16 g_dcats[(size_t)NTOT * 1536];    // dcat split [h(768)|l(768)]
__device__ __align__(256) bf16 g_xxs  [(size_t)NTOT * 512];     // xx split
__device__ __align__(256) bf16 g_gts  [(size_t)NTOT * 512];     // gated split

__device__ __align__(256) float g_Wp[CC * 3 * CC];              // merged proj fp32 (256,768)
__device__ __align__(256) float g_Wkvr[3 * CC * CC];            // merged kvr fp32 (768,256)
__device__ __align__(256) bf16 g_W1s  [CC * 768];               // conv1 split  (256, 768)
__device__ __align__(256) bf16 g_Wps  [CC * 2304];              // proj  split  (256, 2304)
__device__ __align__(256) bf16 g_Wkvrs[768 * 1536];             // kvr   split  (768, 1536)
__device__ __align__(256) bf16 g_Wouts[CC * 768];               // out   split  (256, 768)
__device__ __align__(256) float g_mixcat[3 * CC];
__device__ __align__(256) float g_wneg[CC];
__device__ __align__(256) float g_u[CC];

// ---------------- helpers ----------------
__device__ __forceinline__ uint32_t smem_u32(const void* p) {
    uint32_t a;
    asm("{ .reg .u64 t; cvta.to.shared.u64 t, %1; cvt.u32.u64 %0, t; }" : "=r"(a) : "l"(p));
    return a;
}
__device__ __forceinline__ void st128s(uint32_t addr, uint4 v) {
    asm volatile("st.shared.v4.b32 [%0], {%1, %2, %3, %4};"
                 :: "r"(addr), "r"(v.x), "r"(v.y), "r"(v.z), "r"(v.w) : "memory");
}
__device__ __forceinline__ void ldsm4(uint32_t* r, uint32_t addr) {
    asm volatile("ldmatrix.sync.aligned.m8n8.x4.shared.b16 {%0, %1, %2, %3}, [%4];"
                 : "=r"(r[0]), "=r"(r[1]), "=r"(r[2]), "=r"(r[3]) : "r"(addr));
}
__device__ __forceinline__ void mma16816(float* c, const uint32_t* a, const uint32_t* b) {
    asm volatile(
        "mma.sync.aligned.m16n8k16.row.col.f32.bf16.bf16.f32 "
        "{%0, %1, %2, %3}, {%4, %5, %6, %7}, {%8, %9}, {%0, %1, %2, %3};"
        : "+f"(c[0]), "+f"(c[1]), "+f"(c[2]), "+f"(c[3])
        : "r"(a[0]), "r"(a[1]), "r"(a[2]), "r"(a[3]), "r"(b[0]), "r"(b[1]));
}
__device__ __forceinline__ void bsplit(float v, bf16& h, bf16& l) {
    h = __float2bfloat16(v);
    l = __float2bfloat16(v - __bfloat162float(h));
}

// ---------------- prep 1: merged fp32 weights + wkv constants ----------------
__global__ void prep_kernel(const float* __restrict__ proj1, const float* __restrict__ proj2,
                            const float* __restrict__ proj3,
                            const float* __restrict__ keyw, const float* __restrict__ valw,
                            const float* __restrict__ recw,
                            const float* __restrict__ mixk, const float* __restrict__ mixv,
                            const float* __restrict__ mixr,
                            const float* __restrict__ decay, const float* __restrict__ first)
{
    int i = blockIdx.x * blockDim.x + threadIdx.x;
    if (i < CC * 3 * CC) {
        int o = i / (3 * CC);
        int rem = i % (3 * CC);
        int j = rem >> 8;
        int c = rem & 255;
        const float* p = (j == 0) ? proj1 : (j == 1) ? proj2 : proj3;
        g_Wp[i] = p[o * CC + c];
        g_Wkvr[i] = (i < CC * CC) ? keyw[i]
                  : (i < 2 * CC * CC) ? valw[i - CC * CC]
                  : recw[i - 2 * CC * CC];
    }
    if (i < 3 * CC)
        g_mixcat[i] = (i < CC) ? mixk[i] : (i < 2 * CC) ? mixv[i - CC] : mixr[i - 2 * CC];
    if (i < CC) {
        g_wneg[i] = -expf(decay[i] * (1.0f / (float)TT));
        g_u[i]    = first[i] * (1.0f / (float)TT);
    }
}

// ---------------- prep 2: split weights into [Wh | Wh | Wl] bf16 layouts ----------------
__global__ void prep2_kernel(const float* __restrict__ conv1w, const float* __restrict__ outw)
{
    int i = blockIdx.x * blockDim.x + threadIdx.x;   // up to 196608
    if (i < CC * CC) {
        bf16 h, l;
        bsplit(conv1w[i], h, l);
        int o = i >> 8, k = i & 255;
        g_W1s[o * 768 + k] = h; g_W1s[o * 768 + 256 + k] = h; g_W1s[o * 768 + 512 + k] = l;
        bsplit(outw[i], h, l);
        g_Wouts[o * 768 + k] = h; g_Wouts[o * 768 + 256 + k] = h; g_Wouts[o * 768 + 512 + k] = l;
    }
    if (i < CC * 768) {
        bf16 h, l;
        bsplit(g_Wp[i], h, l);
        int o = i / 768, k = i % 768;
        g_Wps[o * 2304 + k] = h; g_Wps[o * 2304 + 768 + k] = h; g_Wps[o * 2304 + 1536 + k] = l;
    }
    if (i < 768 * CC) {
        int o = i >> 8, c = i & 255;
        float w = g_Wkvr[i];
        float m = g_mixcat[(o >> 8) * CC + c];
        float v1 = w * m, v2 = w * (1.f - m);
        bf16 h1, l1, h2, l2;
        bsplit(v1, h1, l1); bsplit(v2, h2, l2);
        bf16* row = g_Wkvrs + (size_t)o * 1536;
        row[c] = h1;        row[256 + c] = h2;
        row[512 + c] = h1;  row[768 + c] = h2;
        row[1024 + c] = l1; row[1280 + c] = l2;
    }
}

// ---------------- split x fp32 -> [h|l] bf16 ----------------
__global__ void split_x_kernel(const float* __restrict__ x)
{
    size_t i = (size_t)blockIdx.x * blockDim.x + threadIdx.x;   // NTOT*64 quads
    size_t n = i >> 6;
    int q = (int)(i & 63);
    float4 v = *(const float4*)(x + n * 256 + q * 4);
    bf16 h0, l0, h1, l1, h2, l2, h3, l3;
    bsplit(v.x, h0, l0); bsplit(v.y, h1, l1); bsplit(v.z, h2, l2); bsplit(v.w, h3, l3);
    bf16* row = g_xs + n * 512;
    *(bf162*)(row + q * 4)       = bf162(h0, h1);
    *(bf162*)(row + q * 4 + 2)   = bf162(h2, h3);
    *(bf162*)(row + 256 + q * 4)     = bf162(l0, l1);
    *(bf162*)(row + 256 + q * 4 + 2) = bf162(l2, l3);
}

// ---------------- mma.sync GEMM ----------------
// C(n, m) = sum over split schedule: A'(n, K') · W'(m, K')^T
// Block tile 128(n) x 128(m), KB=32, double-buffered smem, 8 warps of 64x32.
// Swizzle: 16B-chunk index ^= (row>>1)&3  (conflict-free for STS.128 and ldmatrix).
// EPI 0: fp32 store to fout (row width MOUT).
// EPI 1: v = D + xadd, hi/lo split store to bout (row width 512).
template <int NIT, int Q, int KH, int SA, bool DUAL, int KW, int MOUT, int EPI>
__device__ __forceinline__ void
gemm_mma_body(const bf16* __restrict__ A0, const bf16* __restrict__ A1,
              const bf16* __restrict__ Wm, const float* __restrict__ xadd,
              float* __restrict__ fout, bf16* __restrict__ bout)
{
    __shared__ __align__(128) bf16 sA[2][128 * 32];
    __shared__ __align__(128) bf16 sB[2][128 * 32];

    const int tid = threadIdx.x;
    const int lane = tid & 31, wid = tid >> 5;
    const int wn = wid >> 2;          // 0..1 : 64-token slab
    const int wm = wid & 3;           // 0..3 : 32-output slab
    const size_t n0 = (size_t)blockIdx.y * 128;
    const int m0 = blockIdx.x * 128;

    // ---- global->smem staging (ldg to regs, sts swizzled) ----
    const int lrow = tid >> 1, half = tid & 1;
    const bf16* aR0 = A0 + (n0 + lrow) * SA + half * 16;
    const bf16* aR1 = DUAL ? (A1 + (n0 + lrow) * SA + half * 16) : aR0;
    const bf16* wR  = Wm + (size_t)(m0 + lrow) * KW + half * 16;

    uint4 ra[2], rb[2];
    auto ldg = [&](int t) {
        int p = t / Q, r = t - p * Q;
        const bf16* base;
        int off;
        if (DUAL) { base = (r >> 3) ? aR1 : aR0; off = ((p == 1) ? KH : 0) + (r & 7) * 32; }
        else      { base = aR0;                  off = ((p == 1) ? KH : 0) + r * 32; }
        const uint4* pa = (const uint4*)(base + off);
        ra[0] = pa[0]; ra[1] = pa[1];
        const uint4* pb = (const uint4*)(wR + t * 32);
        rb[0] = pb[0]; rb[1] = pb[1];
    };

    const uint32_t aBase = smem_u32(sA);
    const uint32_t bBase = smem_u32(sB);
    const int swz = (lrow >> 1) & 3;
    const uint32_t so0 = lrow * 64 + (((half * 2 + 0) ^ swz) << 4);
    const uint32_t so1 = lrow * 64 + (((half * 2 + 1) ^ swz) << 4);
    auto sts = [&](int buf) {
        uint32_t aB = aBase + buf * 8192, bB = bBase + buf * 8192;
        st128s(aB + so0, ra[0]); st128s(aB + so1, ra[1]);
        st128s(bB + so0, rb[0]); st128s(bB + so1, rb[1]);
    };

    // ---- ldmatrix addressing (row = base + (lane&15), chunk-hi = lane>>4) ----
    const int r15 = lane & 15, chi = lane >> 4;
    uint32_t baseA[4], swzA[4];
#pragma unroll
    for (int i = 0; i < 4; ++i) {
        int row = wn * 64 + i * 16 + r15;
        baseA[i] = row * 64;
        swzA[i] = (row >> 1) & 3;
    }
    uint32_t baseB[2], swzB[2];
#pragma unroll
    for (int jp = 0; jp < 2; ++jp) {
        int row = wm * 32 + jp * 16 + r15;
        baseB[jp] = row * 64;
        swzB[jp] = (row >> 1) & 3;
    }

    float acc[4][4][4];
#pragma unroll
    for (int i = 0; i < 4; ++i)
#pragma unroll
        for (int j = 0; j < 4; ++j)
#pragma unroll
            for (int q = 0; q < 4; ++q) acc[i][j][q] = 0.f;

    auto compute = [&](int buf) {
        uint32_t aB = aBase + buf * 8192, bB = bBase + buf * 8192;
#pragma unroll
        for (int s = 0; s < 2; ++s) {
            uint32_t a[4][4], b[4][2];
            uint32_t ck = (uint32_t)(s * 2 + chi);
#pragma unroll
            for (int i = 0; i < 4; ++i)
                ldsm4(a[i], aB + baseA[i] + ((ck ^ swzA[i]) << 4));
#pragma unroll
            for (int jp = 0; jp < 2; ++jp) {
                uint32_t r[4];
                ldsm4(r, bB + baseB[jp] + ((ck ^ swzB[jp]) << 4));
                b[jp * 2][0] = r[0]; b[jp * 2 + 1][0] = r[1];
                b[jp * 2][1] = r[2]; b[jp * 2 + 1][1] = r[3];
            }
#pragma unroll
            for (int i = 0; i < 4; ++i)
#pragma unroll
                for (int j = 0; j < 4; ++j)
                    mma16816(acc[i][j], a[i], b[j]);
        }
    };

    // ---- main loop: double-buffered, one sync per iteration ----
    ldg(0);
    sts(0);
    __syncthreads();
    for (int t = 0; t < NIT; ++t) {
        if (t + 1 < NIT) ldg(t + 1);
        compute(t & 1);
        if (t + 1 < NIT) sts((t + 1) & 1);
        __syncthreads();
    }

    // ---- epilogue: regs -> global ----
    const int g = lane >> 2, c2 = (lane & 3) * 2;
#pragma unroll
    for (int i = 0; i < 4; ++i) {
        size_t r0 = n0 + wn * 64 + i * 16 + g;
        size_t r1 = r0 + 8;
#pragma unroll
        for (int j = 0; j < 4; ++j) {
            int col = m0 + wm * 32 + j * 8 + c2;
            if (EPI == 0) {
                *(float2*)(fout + r0 * MOUT + col) = make_float2(acc[i][j][0], acc[i][j][1]);
                *(float2*)(fout + r1 * MOUT + col) = make_float2(acc[i][j][2], acc[i][j][3]);
            } else {
                float v0 = acc[i][j][0] + xadd[r0 * 256 + col];
                float v1 = acc[i][j][1] + xadd[r0 * 256 + col + 1];
                float v2 = acc[i][j][2] + xadd[r1 * 256 + col];
                float v3 = acc[i][j][3] + xadd[r1 * 256 + col + 1];
                bf16 h0, l0, h1, l1, h2, l2, h3, l3;
                bsplit(v0, h0, l0); bsplit(v1, h1, l1);
                bsplit(v2, h2, l2); bsplit(v3, h3, l3);
                *(bf162*)(bout + r0 * 512 + col)       = bf162(h0, h1);
                *(bf162*)(bout + r0 * 512 + 256 + col) = bf162(l0, l1);
                *(bf162*)(bout + r1 * 512 + col)       = bf162(h2, h3);
                *(bf162*)(bout + r1 * 512 + 256 + col) = bf162(l2, l3);
            }
        }
    }
}

// wrappers bind scratch globals at compile time
__global__ void __launch_bounds__(256, 2) g1_tc() {
    gemm_mma_body<24, 8, 256, 512, false, 768, 256, 0>(g_xs, nullptr, g_W1s, nullptr, g_mid, nullptr);
}
__global__ void __launch_bounds__(256, 2) g2_tc(const float* __restrict__ x) {
    gemm_mma_body<72, 24, 768, 1536, false, 2304, 256, 1>(g_dcats, nullptr, g_Wps, x, nullptr, g_xxs);
}
__global__ void __launch_bounds__(256, 2) g3_tc() {
    gemm_mma_body<48, 16, 256, 512, true, 1536, 768, 0>(g_xs, g_xxs, g_Wkvrs, nullptr, g_kvr, nullptr);
}
__global__ void __launch_bounds__(256, 2) g4_tc(float* __restrict__ out) {
    gemm_mma_body<24, 8, 256, 512, false, 768, 256, 0>(g_gts, nullptr, g_Wouts, nullptr, out, nullptr);
}

// ---------------- fused depthwise 3x3 (dilations 1,2,3), split-bf16 output ----------------
__global__ void __launch_bounds__(256)
dwconv_kernel(const float* __restrict__ dw1, const float* __restrict__ dw2,
              const float* __restrict__ dw3)
{
    __shared__ float s[14 * 14 * 32];
    __shared__ float sw[3 * 32 * 9];

    const int tid = threadIdx.x;
    const int tile = blockIdx.x;
    const int b = blockIdx.y;
    const int cslab = blockIdx.z;
    const int th = tile >> 4, tw = tile & 15;
    const int h0 = th * 8 - 3, w0 = tw * 8 - 3;
    const int cbase = cslab * 32;

    for (int f = tid; f < 864; f += 256) {
        int j = f / 288, rem = f % 288;
        int c = rem / 9, tap = rem % 9;
        const float* wsrc = (j == 0) ? dw1 : (j == 1) ? dw2 : dw3;
        sw[f] = wsrc[(cbase + c) * 9 + tap];
    }

    const int lane = tid & 31, warp = tid >> 5;
    for (int p = warp; p < 196; p += 8) {
        int hy = p / 14, wx = p % 14;
        int h = h0 + hy, w = w0 + wx;
        float v = 0.f;
        if ((unsigned)h < (unsigned)HH && (unsigned)w < (unsigned)WW)
            v = g_mid[((size_t)(b * TT + h * WW + w)) * CC + cbase + lane];
        s[p * 32 + lane] = v;
    }
    __syncthreads();

    const float* w0p = &sw[lane * 9];
    const float* w1p = &sw[288 + lane * 9];
    const float* w2p = &sw[576 + lane * 9];

#pragma unroll
    for (int q = 0; q < 8; ++q) {
        const int oh = warp, ow = q;
        const int hy = oh + 3, wx = ow + 3;
        float acc0 = 0.f, acc1 = 0.f, acc2 = 0.f;
#pragma unroll
        for (int dy = -1; dy <= 1; ++dy) {
#pragma unroll
            for (int dx = -1; dx <= 1; ++dx) {
                int tap = (dy + 1) * 3 + (dx + 1);
                acc0 = fmaf(w0p[tap], s[((hy + dy) * 14 + (wx + dx)) * 32 + lane], acc0);
                acc1 = fmaf(w1p[tap], s[((hy + 2 * dy) * 14 + (wx + 2 * dx)) * 32 + lane], acc1);
                acc2 = fmaf(w2p[tap], s[((hy + 3 * dy) * 14 + (wx + 3 * dx)) * 32 + lane], acc2);
            }
        }
        size_t n = (size_t)b * TT + (size_t)(th * 8 + oh) * WW + (tw * 8 + ow);
        bf16* row = g_dcats + n * 1536;
        bf16 h, l;
        bsplit(acc0, h, l); row[cbase + lane] = h;       row[768 + cbase + lane] = l;
        bsplit(acc1, h, l); row[256 + cbase + lane] = h; row[1024 + cbase + lane] = l;
        bsplit(acc2, h, l); row[512 + cbase + lane] = h; row[1280 + cbase + lane] = l;
    }
}

// ---------------- WKV: halo-recompute chunked scan ----------------
#define WKV_CHUNK 128
#define WKV_HALO 96

__global__ void __launch_bounds__(256)
wkv_kernel()
{
    const int c = threadIdx.x;
    const int b = blockIdx.y;
    const int chunk = blockIdx.x;
    const float wn = g_wneg[c];
    const float uu = g_u[c];

    const int t0 = chunk * WKV_CHUNK;
    int ts = t0 - WKV_HALO;
    if (ts < 0) ts = 0;

    float aa = 0.f, bb = 0.f, pp = -1e38f;

    const float* kv = g_kvr + ((size_t)b * TT + ts) * 768;
    for (int t = ts; t < t0; ++t, kv += 768) {
        float kk = kv[c], vv = kv[256 + c];
        float ww2 = wn + pp;
        if (kk >= ww2) {
            float e = __expf(ww2 - kk);
            aa = fmaf(aa, e, vv);
            bb = fmaf(bb, e, 1.f);
            pp = kk;
        } else {
            float e = __expf(kk - ww2);
            aa = fmaf(e, vv, aa);
            bb += e;
            pp = ww2;
        }
    }

    float* yp = g_y + ((size_t)b * TT + t0) * CC;
#pragma unroll 4
    for (int t = 0; t < WKV_CHUNK; ++t, kv += 768, yp += CC) {
        float kk = kv[c], vv = kv[256 + c];
        float ww = uu + kk;
        float y;
        if (pp >= ww) {
            float e = __expf(ww - pp);
            y = fmaf(e, vv, aa) / (bb + e);
        } else {
            float e = __expf(pp - ww);
            y = fmaf(e, aa, vv) / fmaf(e, bb, 1.f);
        }
        yp[c] = y;

        float ww2 = wn + pp;
        if (kk >= ww2) {
            float e = __expf(ww2 - kk);
            aa = fmaf(aa, e, vv);
            bb = fmaf(bb, e, 1.f);
            pp = kk;
        } else {
            float e = __expf(kk - ww2);
            aa = fmaf(e, vv, aa);
            bb += e;
            pp = ww2;
        }
    }
}

// ---------------- LayerNorm + sigmoid gate -> split bf16 ----------------
__global__ void __launch_bounds__(256)
lngate_kernel(const float* __restrict__ gamma, const float* __restrict__ beta)
{
    const int warp = threadIdx.x >> 5, lane = threadIdx.x & 31;
    const size_t row = (size_t)blockIdx.x * 8 + warp;

    const float* yp = g_y + row * CC;
    float v[8];
    float sum = 0.f;
#pragma unroll
    for (int i = 0; i < 8; ++i) {
        v[i] = yp[lane + 32 * i];
        sum += v[i];
    }
#pragma unroll
    for (int o = 16; o; o >>= 1) sum += __shfl_xor_sync(0xffffffffu, sum, o);
    const float mu = sum * (1.f / 256.f);

    float var = 0.f;
#pragma unroll
    for (int i = 0; i < 8; ++i) {
        float d = v[i] - mu;
        var += d * d;
    }
#pragma unroll
    for (int o = 16; o; o >>= 1) var += __shfl_xor_sync(0xffffffffu, var, o);
    const float rstd = rsqrtf(var * (1.f / 256.f) + 1e-5f);

    const float* rp = g_kvr + row * 768 + 512;
    bf16* gp = g_gts + row * 512;
#pragma unroll
    for (int i = 0; i < 8; ++i) {
        int c = lane + 32 * i;
        float rr = rp[c];
        float sr = 1.f / (1.f + __expf(-rr));
        float gv = sr * ((v[i] - mu) * rstd * gamma[c] + beta[c]);
        bf16 h, l;
        bsplit(gv, h, l);
        gp[c] = h;
        gp[256 + c] = l;
    }
}

// ---------------- launch: pure kernel launches ----------------
extern "C" void kernel_launch(void* const* d_in, const int* in_sizes, int n_in,
                              void* d_out, int out_size)
{
    const float* x      = (const float*)d_in[0];
    const float* conv1w = (const float*)d_in[1];
    const float* dw1    = (const float*)d_in[2];
    const float* dw2    = (const float*)d_in[3];
    const float* dw3    = (const float*)d_in[4];
    const float* proj1  = (const float*)d_in[5];
    const float* proj2  = (const float*)d_in[6];
    const float* proj3  = (const float*)d_in[7];
    const float* decay  = (const float*)d_in[8];
    const float* first  = (const float*)d_in[9];
    const float* mixk   = (const float*)d_in[10];
    const float* mixv   = (const float*)d_in[11];
    const float* mixr   = (const float*)d_in[12];
    const float* keyw   = (const float*)d_in[13];
    const float* valw   = (const float*)d_in[14];
    const float* recw   = (const float*)d_in[15];
    const float* outw   = (const float*)d_in[16];
    const float* gamma  = (const float*)d_in[17];
    const float* beta   = (const float*)d_in[18];
    float* out = (float*)d_out;

    prep_kernel<<<768, 256>>>(proj1, proj2, proj3, keyw, valw, recw,
                              mixk, mixv, mixr, decay, first);
    prep2_kernel<<<768, 256>>>(conv1w, outw);
    split_x_kernel<<<NTOT / 4, 256>>>(x);              // NTOT*64 quads / 256

    // grid: x = m-blocks (few, launched fastest -> A-tile L2 reuse), y = n-blocks
    g1_tc<<<dim3(2, 512), 256>>>();                    // mid = x @ conv1^T (fp32)
    dwconv_kernel<<<dim3(256, 4, 8), 256>>>(dw1, dw2, dw3);
    g2_tc<<<dim3(2, 512), 256>>>(x);                   // xx' = split(x + dcat @ Wp^T)
    g3_tc<<<dim3(6, 512), 256>>>();                    // kvr (mix folded into weights)
    wkv_kernel<<<dim3(TT / WKV_CHUNK, BATCH), 256>>>();
    lngate_kernel<<<NTOT / 8, 256>>>(gamma, beta);
    g4_tc<<<dim3(2, 512), 256>>>(out);                 // out = gt @ out_w^T
}